// round 1
// baseline (speedup 1.0000x reference)
#include <cuda_runtime.h>

#define B_N   32768
#define FIN   64
#define HID   32
#define E_N   25
#define HG    96
#define BAND_HG 8
#define NBAND 12
#define MB    208      // 8 heads * 26 (25 padded to 26 for f32x2 pairing)
#define ROWS_C 128

// scratch (static device globals — no allocation)
__device__ float g_h2[B_N * HID];          // 4 MB intermediate
__device__ float g_part[128][2 * HID];     // per-block BN partial sums
__device__ float g_scale[HID];
__device__ float g_shift[HID];

__device__ __forceinline__ float selu_f(float x) {
    float p = 1.0507009873554805f * x;
    float n = 1.7580993408473766f * (__expf(x) - 1.0f);  // lambda*alpha
    return x > 0.0f ? p : n;
}

__device__ __forceinline__ unsigned long long pk2(float lo, float hi) {
    unsigned long long r;
    asm("mov.b64 %0, {%1,%2};" : "=l"(r)
        : "r"(__float_as_uint(lo)), "r"(__float_as_uint(hi)));
    return r;
}
__device__ __forceinline__ void upk2(unsigned long long v, float& lo, float& hi) {
    unsigned int a, b;
    asm("mov.b64 {%0,%1}, %2;" : "=r"(a), "=r"(b) : "l"(v));
    lo = __uint_as_float(a); hi = __uint_as_float(b);
}
// packed fp32x2 FMA (FFMA2) — only reachable via PTX
#define FFMA2(d, a, b) asm("fma.rn.f32x2 %0, %1, %2, %0;" : "+l"(d) : "l"(a), "l"(b))

// ---------------------------------------------------------------------------
// Kernel A: h = selu(X@W1+b1); h2 = h@W2+b2; store h2; deterministic BN partials
// grid 128 x 256 threads; one row per thread
// smem: xs[256][65] | w1s[64][32] | w2s[32][32] | b1s,b2s ; hs[256][33] aliases xs
// ---------------------------------------------------------------------------
__global__ void __launch_bounds__(256) kernA(
    const float* __restrict__ X,
    const float* __restrict__ W1, const float* __restrict__ b1,
    const float* __restrict__ W2, const float* __restrict__ b2)
{
    extern __shared__ char sm[];
    float* xs  = (float*)sm;                         // 256*65 = 66560 B
    float* w1s = (float*)(sm + 66560);               // 8192 B
    float* w2s = (float*)(sm + 66560 + 8192);        // 4096 B
    float* b1s = (float*)(sm + 66560 + 8192 + 4096); // 128 B
    float* b2s = b1s + HID;                          // 128 B
    float* hs  = xs;                                 // alias: [256][33]

    int t = threadIdx.x;
    int rowbase = blockIdx.x * 256;
    const float* Xb = X + (size_t)rowbase * FIN;

    for (int i = t; i < 256 * FIN; i += 256) xs[(i >> 6) * 65 + (i & 63)] = Xb[i];
    for (int i = t; i < FIN * HID; i += 256) w1s[i] = W1[i];
    for (int i = t; i < HID * HID; i += 256) w2s[i] = W2[i];
    if (t < HID) { b1s[t] = b1[t]; b2s[t] = b2[t]; }
    __syncthreads();

    // stage 1: acc over j-pairs (f32x2)
    unsigned long long acc[16];
    #pragma unroll
    for (int p = 0; p < 16; p++) acc[p] = pk2(b1s[2 * p], b1s[2 * p + 1]);
    #pragma unroll 4
    for (int k = 0; k < FIN; k++) {
        float xk = xs[t * 65 + k];
        unsigned long long xv = pk2(xk, xk);
        #pragma unroll
        for (int p = 0; p < 16; p++) {
            unsigned long long w = *(const unsigned long long*)&w1s[k * HID + 2 * p];
            FFMA2(acc[p], xv, w);
        }
    }
    float h[HID];
    #pragma unroll
    for (int p = 0; p < 16; p++) {
        float a, b;
        upk2(acc[p], a, b);
        h[2 * p] = selu_f(a); h[2 * p + 1] = selu_f(b);
    }
    __syncthreads();   // xs dead from here (hs aliases it)

    // stage 2
    unsigned long long acc2[16];
    #pragma unroll
    for (int p = 0; p < 16; p++) acc2[p] = pk2(b2s[2 * p], b2s[2 * p + 1]);
    #pragma unroll
    for (int k = 0; k < HID; k++) {
        unsigned long long hv = pk2(h[k], h[k]);
        #pragma unroll
        for (int p = 0; p < 16; p++) {
            unsigned long long w = *(const unsigned long long*)&w2s[k * HID + 2 * p];
            FFMA2(acc2[p], hv, w);
        }
    }
    #pragma unroll
    for (int p = 0; p < 16; p++) {
        float a, b;
        upk2(acc2[p], a, b);
        hs[t * 33 + 2 * p] = a; hs[t * 33 + 2 * p + 1] = b;
    }
    __syncthreads();

    // coalesced vectorized store of h2
    float* H2b = g_h2 + (size_t)rowbase * HID;
    for (int i = t * 4; i < 256 * HID; i += 1024) {
        int r = i >> 5, c = i & 31;
        float4 v = make_float4(hs[r * 33 + c],     hs[r * 33 + c + 1],
                               hs[r * 33 + c + 2], hs[r * 33 + c + 3]);
        *(float4*)(H2b + i) = v;
    }
    // deterministic per-block BN partials (one warp, conflict-free LDS)
    if (t < HID) {
        float s = 0.f, s2 = 0.f;
        for (int r = 0; r < 256; r++) {
            float v = hs[r * 33 + t];
            s += v; s2 += v * v;
        }
        g_part[blockIdx.x][t]       = s;
        g_part[blockIdx.x][HID + t] = s2;
    }
}

// ---------------------------------------------------------------------------
// Kernel B: fold partials -> scale/shift (deterministic)
// ---------------------------------------------------------------------------
__global__ void kernB(const float* __restrict__ gamma, const float* __restrict__ beta) {
    int t = threadIdx.x;  // 32 threads
    float s = 0.f, s2 = 0.f;
    for (int b = 0; b < 128; b++) { s += g_part[b][t]; s2 += g_part[b][HID + t]; }
    float mu  = s  * (1.0f / B_N);
    float var = s2 * (1.0f / B_N) - mu * mu;
    float sc  = gamma[t] * rsqrtf(var + 1e-5f);
    g_scale[t] = sc;
    g_shift[t] = beta[t] - mu * sc;
}

// ---------------------------------------------------------------------------
// Kernel C: e = selu(BN(h2)); D = e @ Wh + bh; selu; L1-normalize per (h,g); write
// grid (12 bands, 256 row-blocks) x 256 threads
// block tile: 128 rows x 8 heads (208 padded m)
// thread: 4 rows x 13 m-pairs (= one full head) -> 52 f32x2 accumulators
// smem: bhs[208] | wch[32][208] | epd[32][128] u64 ; staging (transposed
//       [200][65]) aliases wch+epd after a barrier
// ---------------------------------------------------------------------------
__global__ void __launch_bounds__(256) kernC(
    const float* __restrict__ Wh, const float* __restrict__ bh,
    float* __restrict__ out)
{
    extern __shared__ char sm[];
    float* bhs = (float*)sm;                                    // 832 B
    float* wch = (float*)(sm + 832);                            // 26624 B
    unsigned long long* epd = (unsigned long long*)(sm + 832 + 26624); // 32768 B
    float* stg = (float*)(sm + 832);                            // alias (post-GEMM)

    int t = threadIdx.x;
    int band = blockIdx.x;
    int rowbase = blockIdx.y * ROWS_C;

    // biases (padded col 25 -> 0, never read)
    for (int i = t; i < BAND_HG * 26; i += 256) {
        int hgl = i / 26, j = i - hgl * 26;
        bhs[i] = (j < E_N) ? bh[(band * BAND_HG + hgl) * E_N + j] : 0.0f;
    }
    // weights: Wh[hg][k][j] -> wch[k][hgl*26 + j], zero the pad column
    for (int i = t; i < BAND_HG * HID * E_N; i += 256) {
        int hgl = i / (HID * E_N);
        int rem = i - hgl * HID * E_N;
        int k = rem / E_N, j = rem - k * E_N;
        wch[k * MB + hgl * 26 + j] = Wh[(size_t)(band * BAND_HG + hgl) * HID * E_N + rem];
    }
    for (int i = t; i < HID * BAND_HG; i += 256) {
        int k = i >> 3, hgl = i & 7;
        wch[k * MB + hgl * 26 + 25] = 0.0f;
    }
    // e-tile: BN + selu, stored duplicated (e,e) as f32x2, layout [k][row]
    const float* h2t = g_h2 + (size_t)rowbase * HID;
    for (int i = t; i < ROWS_C * HID; i += 256) {
        int r = i >> 5, k = i & 31;
        float v = h2t[i];
        v = fmaf(v, g_scale[k], g_shift[k]);
        v = selu_f(v);
        epd[k * ROWS_C + r] = pk2(v, v);
    }
    __syncthreads();

    int tx = t & 31;   // row lane: rows {tx, tx+32, tx+64, tx+96}
    int my = t >> 5;   // head within band (warp-uniform -> weight LDS broadcast)
    unsigned long long acc[4][13];
    #pragma unroll
    for (int r = 0; r < 4; r++)
        #pragma unroll
        for (int p = 0; p < 13; p++) acc[r][p] = 0ULL;

    int wb = my * 26;
    #pragma unroll 4
    for (int k = 0; k < HID; k++) {
        unsigned long long e0 = epd[k * ROWS_C + tx];
        unsigned long long e1 = epd[k * ROWS_C + tx + 32];
        unsigned long long e2 = epd[k * ROWS_C + tx + 64];
        unsigned long long e3 = epd[k * ROWS_C + tx + 96];
        #pragma unroll
        for (int p = 0; p < 13; p++) {
            unsigned long long w = *(const unsigned long long*)&wch[k * MB + wb + 2 * p];
            FFMA2(acc[0][p], e0, w);
            FFMA2(acc[1][p], e1, w);
            FFMA2(acc[2][p], e2, w);
            FFMA2(acc[3][p], e3, w);
        }
    }
    __syncthreads();  // all wch/epd reads done; staging may overwrite them

    // epilogue in two 64-row halves (staging transposed [c][r], stride 65:
    // conflict-free STS; readback feeds coalesced STG.128)
    for (int half = 0; half < 2; half++) {
        if (half) __syncthreads();
        #pragma unroll
        for (int ri2 = 0; ri2 < 2; ri2++) {
            int ri = half * 2 + ri2;
            int rstg = tx + 32 * ri2;   // 0..63
            float v[26];
            #pragma unroll
            for (int p = 0; p < 13; p++) upk2(acc[ri][p], v[2 * p], v[2 * p + 1]);
            float s = 0.f;
            #pragma unroll
            for (int j = 0; j < E_N; j++) {
                float d = v[j] + bhs[my * 26 + j];
                d = selu_f(d);
                v[j] = d;
                s += fabsf(d);
            }
            float inv = __fdividef(1.0f, fmaxf(s, 1e-12f));
            #pragma unroll
            for (int j = 0; j < E_N; j++)
                stg[(my * E_N + j) * 65 + rstg] = v[j] * inv;  // sign(d)*|d|/l1 == d/l1
        }
        __syncthreads();
        float* ob = out + (size_t)(rowbase + 64 * half) * HG * E_N + band * BAND_HG * E_N;
        for (int i = t; i < 64 * 50; i += 256) {
            int r = i / 50, q = i - r * 50;
            float4 vv;
            vv.x = stg[(4 * q + 0) * 65 + r];
            vv.y = stg[(4 * q + 1) * 65 + r];
            vv.z = stg[(4 * q + 2) * 65 + r];
            vv.w = stg[(4 * q + 3) * 65 + r];
            *(float4*)(ob + (size_t)r * HG * E_N + 4 * q) = vv;  // 16B aligned
        }
    }
}

// ---------------------------------------------------------------------------
extern "C" void kernel_launch(void* const* d_in, const int* in_sizes, int n_in,
                              void* d_out, int out_size) {
    const float* X     = (const float*)d_in[0];
    const float* W1    = (const float*)d_in[1];
    const float* b1    = (const float*)d_in[2];
    const float* W2    = (const float*)d_in[3];
    const float* b2    = (const float*)d_in[4];
    const float* gamma = (const float*)d_in[5];
    const float* beta  = (const float*)d_in[6];
    const float* Wh    = (const float*)d_in[7];
    const float* bh    = (const float*)d_in[8];
    float* out = (float*)d_out;

    cudaFuncSetAttribute(kernA, cudaFuncAttributeMaxDynamicSharedMemorySize, 79104);
    cudaFuncSetAttribute(kernC, cudaFuncAttributeMaxDynamicSharedMemorySize, 60224);

    kernA<<<128, 256, 79104>>>(X, W1, b1, W2, b2);
    kernB<<<1, 32>>>(gamma, beta);
    kernC<<<dim3(NBAND, 256), 256, 60224>>>(Wh, bh, out);
}

// round 2
// speedup vs baseline: 1.4485x; 1.4485x over previous
#include <cuda_runtime.h>

#define B_N   32768
#define FIN   64
#define HID   32
#define E_N   25
#define HG    96
#define BAND_HG 8
#define NBAND 12
#define MB    208      // 8 heads * 26 (25 padded to 26 for f32x2 pairing)
#define ROWS_C 64      // rows per kernC block
#define EPD_STRIDE 65  // u64 row stride for e-tile (conflict mitigation)

// scratch (static device globals — no allocation)
__device__ float g_h2[B_N * HID];          // 4 MB intermediate
__device__ float g_part[256][2 * HID];     // per-block BN partial sums
__device__ float g_scale[HID];
__device__ float g_shift[HID];

__device__ __forceinline__ float selu_f(float x) {
    float p = 1.0507009873554805f * x;
    float n = 1.7580993408473766f * (__expf(x) - 1.0f);  // lambda*alpha
    return x > 0.0f ? p : n;
}

__device__ __forceinline__ unsigned long long pk2(float lo, float hi) {
    unsigned long long r;
    asm("mov.b64 %0, {%1,%2};" : "=l"(r)
        : "r"(__float_as_uint(lo)), "r"(__float_as_uint(hi)));
    return r;
}
__device__ __forceinline__ void upk2(unsigned long long v, float& lo, float& hi) {
    unsigned int a, b;
    asm("mov.b64 {%0,%1}, %2;" : "=r"(a), "=r"(b) : "l"(v));
    lo = __uint_as_float(a); hi = __uint_as_float(b);
}
// packed fp32x2 FMA (FFMA2) — only reachable via PTX
#define FFMA2(d, a, b) asm("fma.rn.f32x2 %0, %1, %2, %0;" : "+l"(d) : "l"(a), "l"(b))

// ---------------------------------------------------------------------------
// Kernel A: h = selu(X@W1+b1); h2 = h@W2+b2; store h2; deterministic BN partials
// grid 256 x 128 threads; 128 rows/block, one row per thread
// smem: xs[128][65] | w1s[64][32] | w2s[32][32] | b1s,b2s ; hs[128][33] aliases xs
// ---------------------------------------------------------------------------
__global__ void __launch_bounds__(128) kernA(
    const float* __restrict__ X,
    const float* __restrict__ W1, const float* __restrict__ b1,
    const float* __restrict__ W2, const float* __restrict__ b2)
{
    extern __shared__ char sm[];
    float* xs  = (float*)sm;                         // 128*65*4 = 33280 B
    float* w1s = (float*)(sm + 33280);               // 8192 B
    float* w2s = (float*)(sm + 33280 + 8192);        // 4096 B
    float* b1s = (float*)(sm + 33280 + 8192 + 4096); // 128 B
    float* b2s = b1s + HID;                          // 128 B
    float* hs  = xs;                                 // alias: [128][33]

    int t = threadIdx.x;
    int rowbase = blockIdx.x * 128;
    const float* Xb = X + (size_t)rowbase * FIN;

    for (int i = t; i < 128 * FIN; i += 128) xs[(i >> 6) * 65 + (i & 63)] = Xb[i];
    for (int i = t; i < FIN * HID; i += 128) w1s[i] = W1[i];
    for (int i = t; i < HID * HID; i += 128) w2s[i] = W2[i];
    if (t < HID) { b1s[t] = b1[t]; b2s[t] = b2[t]; }
    __syncthreads();

    // stage 1: acc over j-pairs (f32x2)
    unsigned long long acc[16];
    #pragma unroll
    for (int p = 0; p < 16; p++) acc[p] = pk2(b1s[2 * p], b1s[2 * p + 1]);
    #pragma unroll 4
    for (int k = 0; k < FIN; k++) {
        float xk = xs[t * 65 + k];
        unsigned long long xv = pk2(xk, xk);
        #pragma unroll
        for (int p = 0; p < 16; p++) {
            unsigned long long w = *(const unsigned long long*)&w1s[k * HID + 2 * p];
            FFMA2(acc[p], xv, w);
        }
    }
    float h[HID];
    #pragma unroll
    for (int p = 0; p < 16; p++) {
        float a, b;
        upk2(acc[p], a, b);
        h[2 * p] = selu_f(a); h[2 * p + 1] = selu_f(b);
    }
    __syncthreads();   // xs dead from here (hs aliases it)

    // stage 2
    unsigned long long acc2[16];
    #pragma unroll
    for (int p = 0; p < 16; p++) acc2[p] = pk2(b2s[2 * p], b2s[2 * p + 1]);
    #pragma unroll
    for (int k = 0; k < HID; k++) {
        unsigned long long hv = pk2(h[k], h[k]);
        #pragma unroll
        for (int p = 0; p < 16; p++) {
            unsigned long long w = *(const unsigned long long*)&w2s[k * HID + 2 * p];
            FFMA2(acc2[p], hv, w);
        }
    }
    #pragma unroll
    for (int p = 0; p < 16; p++) {
        float a, b;
        upk2(acc2[p], a, b);
        hs[t * 33 + 2 * p] = a; hs[t * 33 + 2 * p + 1] = b;
    }
    __syncthreads();

    // coalesced vectorized store of h2
    float* H2b = g_h2 + (size_t)rowbase * HID;
    for (int i = t * 4; i < 128 * HID; i += 512) {
        int r = i >> 5, c = i & 31;
        float4 v = make_float4(hs[r * 33 + c],     hs[r * 33 + c + 1],
                               hs[r * 33 + c + 2], hs[r * 33 + c + 3]);
        *(float4*)(H2b + i) = v;
    }
    // deterministic per-block BN partials (one warp, conflict-free LDS)
    if (t < HID) {
        float s = 0.f, s2 = 0.f;
        for (int r = 0; r < 128; r++) {
            float v = hs[r * 33 + t];
            s += v; s2 += v * v;
        }
        g_part[blockIdx.x][t]       = s;
        g_part[blockIdx.x][HID + t] = s2;
    }
}

// ---------------------------------------------------------------------------
// Kernel B: fold partials -> scale/shift (deterministic)
// ---------------------------------------------------------------------------
__global__ void kernB(const float* __restrict__ gamma, const float* __restrict__ beta) {
    int t = threadIdx.x;  // 32 threads
    float s = 0.f, s2 = 0.f;
    for (int b = 0; b < 256; b++) { s += g_part[b][t]; s2 += g_part[b][HID + t]; }
    float mu  = s  * (1.0f / B_N);
    float var = s2 * (1.0f / B_N) - mu * mu;
    float sc  = gamma[t] * rsqrtf(var + 1e-5f);
    g_scale[t] = sc;
    g_shift[t] = beta[t] - mu * sc;
}

// ---------------------------------------------------------------------------
// Kernel C: e = selu(BN(h2)); D = e @ Wh + bh; selu; L1-normalize per (h,g); write
// grid (12 bands, 512 row-blocks) x 256 threads
// block tile: 64 rows x 8 heads (208 padded m)
// thread: 2 rows x 13 m-pairs (= one full head) -> 26 f32x2 accumulators (52 regs)
// smem: bhs[208] | wch[32][208] f32 | epd[32][65] u64
//       staging (transposed [200][33]) aliases wch after GEMM barrier
// ---------------------------------------------------------------------------
__global__ void __launch_bounds__(256) kernC(
    const float* __restrict__ Wh, const float* __restrict__ bh,
    float* __restrict__ out)
{
    extern __shared__ char sm[];
    float* bhs = (float*)sm;                                    // 832 B
    float* wch = (float*)(sm + 832);                            // 26624 B
    unsigned long long* epd = (unsigned long long*)(sm + 832 + 26624); // 32*65*8 = 16640 B
    float* stg = (float*)(sm + 832);                            // alias (post-GEMM), 200*33*4 = 26400 B

    int t = threadIdx.x;
    int band = blockIdx.x;
    int rowbase = blockIdx.y * ROWS_C;

    // biases (padded col 25 -> 0, never read)
    for (int i = t; i < BAND_HG * 26; i += 256) {
        int hgl = i / 26, j = i - hgl * 26;
        bhs[i] = (j < E_N) ? bh[(band * BAND_HG + hgl) * E_N + j] : 0.0f;
    }
    // weights: Wh[hg][k][j] -> wch[k][hgl*26 + j], zero the pad column
    for (int i = t; i < BAND_HG * HID * E_N; i += 256) {
        int hgl = i / (HID * E_N);
        int rem = i - hgl * HID * E_N;
        int k = rem / E_N, j = rem - k * E_N;
        wch[k * MB + hgl * 26 + j] = Wh[(size_t)(band * BAND_HG + hgl) * HID * E_N + rem];
    }
    for (int i = t; i < HID * BAND_HG; i += 256) {
        int k = i >> 3, hgl = i & 7;
        wch[k * MB + hgl * 26 + 25] = 0.0f;
    }
    // e-tile: BN + selu, stored duplicated (e,e) as f32x2, layout [k][row] stride 65
    const float* h2t = g_h2 + (size_t)rowbase * HID;
    for (int i = t; i < ROWS_C * HID; i += 256) {
        int r = i >> 5, k = i & 31;
        float v = h2t[i];
        v = fmaf(v, g_scale[k], g_shift[k]);
        v = selu_f(v);
        epd[k * EPD_STRIDE + r] = pk2(v, v);
    }
    __syncthreads();

    int tx = t & 31;   // row lane: rows {tx, tx+32}
    int my = t >> 5;   // head within band (warp-uniform -> weight LDS broadcast)
    unsigned long long acc[2][13];
    #pragma unroll
    for (int r = 0; r < 2; r++)
        #pragma unroll
        for (int p = 0; p < 13; p++) acc[r][p] = 0ULL;

    int wb = my * 26;
    #pragma unroll 4
    for (int k = 0; k < HID; k++) {
        unsigned long long e0 = epd[k * EPD_STRIDE + tx];
        unsigned long long e1 = epd[k * EPD_STRIDE + tx + 32];
        #pragma unroll
        for (int p = 0; p < 13; p++) {
            unsigned long long w = *(const unsigned long long*)&wch[k * MB + wb + 2 * p];
            FFMA2(acc[0][p], e0, w);
            FFMA2(acc[1][p], e1, w);
        }
    }
    __syncthreads();  // all wch/epd reads done; staging may overwrite wch

    // epilogue: two 32-row halves; staging transposed [m][r] stride 33
    #pragma unroll
    for (int ri = 0; ri < 2; ri++) {
        if (ri) __syncthreads();
        {
            float v[26];
            #pragma unroll
            for (int p = 0; p < 13; p++) upk2(acc[ri][p], v[2 * p], v[2 * p + 1]);
            float s = 0.f;
            #pragma unroll
            for (int j = 0; j < E_N; j++) {
                float d = v[j] + bhs[my * 26 + j];
                d = selu_f(d);
                v[j] = d;
                s += fabsf(d);
            }
            float inv = __fdividef(1.0f, fmaxf(s, 1e-12f));
            #pragma unroll
            for (int j = 0; j < E_N; j++)
                stg[(my * E_N + j) * 33 + tx] = v[j] * inv;  // sign(d)*|d|/l1 == d/l1
        }
        __syncthreads();
        // write 32 rows x 200 cols, coalesced STG.128
        float* ob = out + (size_t)(rowbase + 32 * ri) * HG * E_N + band * BAND_HG * E_N;
        for (int i = t; i < 32 * 50; i += 256) {
            int r = i / 50, q = i - r * 50;
            float4 vv;
            vv.x = stg[(4 * q + 0) * 33 + r];
            vv.y = stg[(4 * q + 1) * 33 + r];
            vv.z = stg[(4 * q + 2) * 33 + r];
            vv.w = stg[(4 * q + 3) * 33 + r];
            *(float4*)(ob + (size_t)r * HG * E_N + 4 * q) = vv;  // 16B aligned
        }
    }
}

// ---------------------------------------------------------------------------
extern "C" void kernel_launch(void* const* d_in, const int* in_sizes, int n_in,
                              void* d_out, int out_size) {
    const float* X     = (const float*)d_in[0];
    const float* W1    = (const float*)d_in[1];
    const float* b1    = (const float*)d_in[2];
    const float* W2    = (const float*)d_in[3];
    const float* b2    = (const float*)d_in[4];
    const float* gamma = (const float*)d_in[5];
    const float* beta  = (const float*)d_in[6];
    const float* Wh    = (const float*)d_in[7];
    const float* bh    = (const float*)d_in[8];
    float* out = (float*)d_out;

    cudaFuncSetAttribute(kernA, cudaFuncAttributeMaxDynamicSharedMemorySize, 46080);
    cudaFuncSetAttribute(kernC, cudaFuncAttributeMaxDynamicSharedMemorySize, 44096);

    kernA<<<256, 128, 46080>>>(X, W1, b1, W2, b2);
    kernB<<<1, 32>>>(gamma, beta);
    kernC<<<dim3(NBAND, 512), 256, 44096>>>(Wh, bh, out);
}